// round 6
// baseline (speedup 1.0000x reference)
#include <cuda_runtime.h>
#include <math.h>

// ---------------------------------------------------------------------------
// RPN forward, batch -1 only.
// pad -> weight transpose (+hist zero) -> 3x3 conv (f32x2 packed FMA) ->
// head GEMM + decode + score-histogram -> bucket prefix -> scatter ->
// exact local rank (top-6000 in order) -> NMS mask (upper triangle, with the
// reference's yy2=max bug) -> chunk-batched serial NMS scan -> 300x4 output.
// ---------------------------------------------------------------------------

#define FSZ   50
#define XP    52
#define NCH   512
#define NKEYS 22500
#define PRE_NMS 6000
#define POST_NMS 300
#define NWORDS 188            // ceil(6000/32)
#define NBUCK 65536

__device__ float  g_Xp[NCH * XP * XP];
__device__ float  g_Wt[9 * NCH * NCH];                 // [tap][ic][oc]
__device__ float  g_feat[FSZ * FSZ * NCH];             // [s][oc]
__device__ float4 g_boxes[NKEYS];
__device__ unsigned g_hi[NKEYS];                       // order key hi (asc = score desc)
__device__ unsigned g_hist[NBUCK];
__device__ unsigned g_bcnt[NBUCK];
__device__ unsigned g_bstart[NBUCK + 1];
__device__ unsigned long long g_skey[NKEYS];
__device__ int    g_C;
__device__ float4 g_sboxes[PRE_NMS];
__device__ unsigned g_mask[PRE_NMS * NWORDS];

#define FMA2(d, a, b) asm("fma.rn.f32x2 %0, %1, %2, %0;" : "+l"(d) : "l"(a), "l"(b))

// ---------------------------------------------------------------------------
__global__ void pad_kernel(const float* __restrict__ in) {
    int idx = blockIdx.x * blockDim.x + threadIdx.x;
    if (idx >= NCH * XP * XP) return;
    int c = idx / (XP * XP);
    int r = idx - c * (XP * XP);
    int y = r / XP, x = r - y * XP;
    float v = 0.0f;
    if (y >= 1 && y <= FSZ && x >= 1 && x <= FSZ)
        v = in[((7 * NCH + c) * FSZ + (y - 1)) * FSZ + (x - 1)];
    g_Xp[idx] = v;
}

// conv_w[oc][ic][kh][kw] -> g_Wt[tap][ic][oc]; also zero histograms.
__global__ void wt_kernel(const float* __restrict__ w) {
    int idx = blockIdx.x * blockDim.x + threadIdx.x;
    if (idx < NBUCK) { g_hist[idx] = 0u; g_bcnt[idx] = 0u; }
    if (idx >= NCH * NCH * 9) return;
    int tap = idx % 9;
    int ic  = (idx / 9) % NCH;
    int oc  = idx / (9 * NCH);
    g_Wt[(tap * NCH + ic) * NCH + oc] = w[idx];
}

// ---------------------------------------------------------------------------
// 3x3 conv: block = 64 oc x 50 w (one row h). 160 threads, 20 outputs each,
// accumulated as 10 packed f32x2 pairs via fma.rn.f32x2.
// ---------------------------------------------------------------------------
__global__ void __launch_bounds__(160) conv_kernel(const float* __restrict__ bias) {
    const int h   = blockIdx.y;
    const int ocb = blockIdx.x * 64;
    const int tid = threadIdx.x;
    const int to  = tid & 15;
    const int tw  = tid >> 4;
    const int wb  = tw * 5;

    __shared__ float  As[8 * 9 * 64];    // [t*9+tap][oc] 18 KB
    __shared__ float2 Bs[8 * 3 * 52];    // duplicated splats, 9.75 KB

    unsigned long long acc[2][5];
#pragma unroll
    for (int p = 0; p < 2; ++p)
#pragma unroll
        for (int j = 0; j < 5; ++j) acc[p][j] = 0ull;

    for (int ic0 = 0; ic0 < NCH; ic0 += 8) {
#pragma unroll
        for (int it = 0; it < 8; ++it) {
            int idx = tid + it * 160;
            if (idx < 1152) {
                int rrow = idx >> 4, col = idx & 15;
                int t = rrow / 9, tap = rrow - t * 9;
                const float4* src = reinterpret_cast<const float4*>(
                    &g_Wt[(tap * NCH + ic0 + t) * NCH + ocb]);
                reinterpret_cast<float4*>(As)[idx] = src[col];
            }
        }
#pragma unroll
        for (int it = 0; it < 8; ++it) {
            int idx = tid + it * 160;
            if (idx < 1248) {
                int t = idx / 156;
                int rem = idx - t * 156;
                int kh = rem / 52, x = rem - kh * 52;
                float v = g_Xp[(ic0 + t) * (XP * XP) + (h + kh) * XP + x];
                Bs[idx] = make_float2(v, v);
            }
        }
        __syncthreads();

#pragma unroll 1
        for (int t = 0; t < 8; ++t) {
#pragma unroll
            for (int kh = 0; kh < 3; ++kh) {
                unsigned long long bsp[7];
                const unsigned long long* bp =
                    reinterpret_cast<const unsigned long long*>(&Bs[(t * 3 + kh) * 52 + wb]);
#pragma unroll
                for (int j = 0; j < 7; ++j) bsp[j] = bp[j];
#pragma unroll
                for (int kw = 0; kw < 3; ++kw) {
                    ulonglong2 a2 = reinterpret_cast<const ulonglong2*>(As)
                        [(t * 9 + kh * 3 + kw) * 16 + to];
#pragma unroll
                    for (int j = 0; j < 5; ++j) {
                        FMA2(acc[0][j], a2.x, bsp[kw + j]);
                        FMA2(acc[1][j], a2.y, bsp[kw + j]);
                    }
                }
            }
        }
        __syncthreads();
    }

    float4 bb = reinterpret_cast<const float4*>(bias)[(ocb >> 2) + to];
#pragma unroll
    for (int j = 0; j < 5; ++j) {
        int s = h * FSZ + wb + j;
        float4 v;
        v.x = __uint_as_float((unsigned)(acc[0][j]))       + bb.x;
        v.y = __uint_as_float((unsigned)(acc[0][j] >> 32)) + bb.y;
        v.z = __uint_as_float((unsigned)(acc[1][j]))       + bb.z;
        v.w = __uint_as_float((unsigned)(acc[1][j] >> 32)) + bb.w;
        v.x = (v.x >= 0.0f) ? v.x : 0.01f * v.x;
        v.y = (v.y >= 0.0f) ? v.y : 0.01f * v.y;
        v.z = (v.z >= 0.0f) ? v.z : 0.01f * v.z;
        v.w = (v.w >= 0.0f) ? v.w : 0.01f * v.w;
        *reinterpret_cast<float4*>(&g_feat[s * NCH + ocb + to * 4]) = v;
    }
}

// ---------------------------------------------------------------------------
// Head: weight-stationary GEMM over 16 spatials/block + decode + histogram.
// dyn smem: Ws[512][64] (131072 B) + ft[16][512] (32768 B) = 163840 B.
// ---------------------------------------------------------------------------
#define HB 16
__global__ void __launch_bounds__(512) head_kernel(const float* __restrict__ rw,
                                                   const float* __restrict__ rb,
                                                   const float* __restrict__ cw,
                                                   const float* __restrict__ cb) {
    extern __shared__ float sh[];
    float* Ws = sh;                // [k*64 + o]
    float* ft = sh + NCH * 64;     // [sl*512 + k]
    __shared__ float bb[64];
    __shared__ float vals[HB * 54];

    const int tid = threadIdx.x;
    const int s0 = blockIdx.x * HB;

    for (int e = tid; e < 54 * NCH; e += 512) {
        int o = e >> 9, k = e & 511;
        Ws[k * 64 + o] = (o < 36) ? rw[o * NCH + k] : cw[(o - 36) * NCH + k];
    }
    if (tid < 54) bb[tid] = (tid < 36) ? rb[tid] : cb[tid - 36];
    for (int e = tid; e < HB * NCH / 4; e += 512) {
        int sl = e >> 7, k4 = e & 127;
        int s = s0 + sl;
        float4 v = make_float4(0.f, 0.f, 0.f, 0.f);
        if (s < FSZ * FSZ) v = reinterpret_cast<const float4*>(g_feat + s * NCH)[k4];
        reinterpret_cast<float4*>(ft + sl * NCH)[k4] = v;
    }
    __syncthreads();

    const int o = tid & 63, g = tid >> 6;     // 8 groups x 2 spatials
    if (o < 54) {
#pragma unroll
        for (int si = 0; si < 2; ++si) {
            int sl = g * 2 + si;
            const float* f = ft + sl * NCH;
            float a = 0.0f;
#pragma unroll 8
            for (int k = 0; k < NCH; ++k) a += Ws[k * 64 + o] * f[k];
            vals[sl * 54 + o] = a + bb[o];
        }
    }
    __syncthreads();

    if (tid < HB * 9) {
        int sl = tid / 9, a = tid - sl * 9;
        int s = s0 + sl;
        if (s < FSZ * FSZ) {
            const float* v = &vals[sl * 54];
            float pr0 = v[a * 4 + 0], pr1 = v[a * 4 + 1];
            float pr2 = v[a * 4 + 2], pr3 = v[a * 4 + 3];
            float l0 = v[36 + a * 2], l1 = v[36 + a * 2 + 1];
            float m = fmaxf(l0, l1);
            float e0 = expf(l0 - m), e1 = expf(l1 - m);
            float score = e1 / (e0 + e1);

            int hh = s / FSZ, ww = s - hh * FSZ;
            float cx = (float)(16 * hh + 8);
            float cy = (float)(16 * ww + 8);
            int r = a / 3, q = a - r * 3;
            float basev = (q == 0) ? 128.0f : (q == 1 ? 256.0f : 512.0f);
            float sq_r  = (r == 0) ? sqrtf(0.5f) : (r == 1 ? 1.0f : sqrtf(2.0f));
            float sq_ir = (r == 0) ? sqrtf(2.0f) : (r == 1 ? 1.0f : sqrtf(0.5f));
            float hsv = basev * sq_r;
            float wsv = basev * sq_ir;
            float ax1 = cx - wsv * 0.5f;
            float ay1 = cy - hsv * 0.5f;

            float t1 = pr0 + ax1;
            float t2 = pr1 + ay1;
            float rx1 = fminf(fmaxf(t1, 0.0f), 799.0f);
            float ry1 = fminf(fmaxf(t2, 0.0f), 799.0f);
            float rx2 = fminf(fmaxf((t1 + pr2) + wsv, 0.0f), 799.0f);
            float ry2 = fminf(fmaxf((t2 + pr3) + hsv, 0.0f), 799.0f);

            float wv = pr2 + wsv, hv = pr3 + hsv;
            bool valid = (wv >= 16.0f) && (hv >= 16.0f);
            float sm = valid ? score : -INFINITY;

            unsigned u = __float_as_uint(sm);
            unsigned vm = (u & 0x80000000u) ? ~u : (u | 0x80000000u);  // ascending in score
            unsigned hi = ~vm;                                          // ascending = score desc
            int gi = s * 9 + a;
            g_hi[gi] = hi;
            atomicAdd(&g_hist[hi >> 16], 1u);
            g_boxes[gi] = make_float4(rx1, ry1, rx2, ry2);
        }
    }
}

// ---------------------------------------------------------------------------
// Exclusive prefix over 65536 buckets; finds candidate cutoff g_C.
// ---------------------------------------------------------------------------
__global__ void __launch_bounds__(1024) prefix_kernel() {
    const int tid = threadIdx.x;
    const int base = tid * 64;
    unsigned sum = 0;
    for (int k = 0; k < 64; ++k) sum += g_hist[base + k];

    unsigned lane = tid & 31, w = tid >> 5;
    unsigned inc = sum;
#pragma unroll
    for (int d = 1; d < 32; d <<= 1) {
        unsigned n = __shfl_up_sync(0xFFFFFFFFu, inc, d);
        if (lane >= d) inc += n;
    }
    __shared__ unsigned wsum[32];
    if (lane == 31) wsum[w] = inc;
    __syncthreads();
    if (w == 0) {
        unsigned x = wsum[lane];
#pragma unroll
        for (int d = 1; d < 32; d <<= 1) {
            unsigned n = __shfl_up_sync(0xFFFFFFFFu, x, d);
            if (lane >= d) x += n;
        }
        wsum[lane] = x;
    }
    __syncthreads();
    unsigned run = inc - sum + (w ? wsum[w - 1] : 0u);
    for (int k = 0; k < 64; ++k) {
        unsigned hcount = g_hist[base + k];
        g_bstart[base + k] = run;
        unsigned nx = run + hcount;
        if (run < PRE_NMS && nx >= PRE_NMS) g_C = (int)nx;
        run = nx;
    }
    if (tid == 1023) g_bstart[NBUCK] = run;
}

__global__ void __launch_bounds__(256) scatter_kernel() {
    int i = blockIdx.x * 256 + threadIdx.x;
    if (i >= NKEYS) return;
    unsigned hi = g_hi[i];
    unsigned b = hi >> 16;
    unsigned st = g_bstart[b];
    if (st < PRE_NMS) {
        unsigned pos = st + atomicAdd(&g_bcnt[b], 1u);
        g_skey[pos] = ((unsigned long long)hi << 15) | (unsigned)i;
    }
}

// Exact stable rank within bucket; scatter top-6000 boxes in rank order.
__global__ void __launch_bounds__(256) localrank_kernel() {
    int p = blockIdx.x * 256 + threadIdx.x;
    if (p >= g_C) return;
    unsigned long long key = g_skey[p];
    unsigned hi = (unsigned)(key >> 15);
    unsigned b = hi >> 16;
    int s = (int)g_bstart[b], e = (int)g_bstart[b + 1];
    int r = s;
    for (int q = s; q < e; ++q) r += (g_skey[q] < key) ? 1 : 0;
    if (r < PRE_NMS) g_sboxes[r] = g_boxes[key & 0x7FFFu];
}

// ---------------------------------------------------------------------------
// NMS mask (upper triangle only), reference bug yy2 = max kept verbatim.
// ---------------------------------------------------------------------------
__global__ void __launch_bounds__(32) mask_kernel() {
    const int bi = blockIdx.y, bj = blockIdx.x;
    if (bj < bi) return;
    const int t = threadIdx.x;
    const int i = bi * 32 + t;

    __shared__ float4 bx[32];
    __shared__ float ar[32];
    const int j0 = bj * 32;
    if (j0 + t < PRE_NMS) {
        float4 b = g_sboxes[j0 + t];
        bx[t] = b;
        ar[t] = ((b.z - b.x) + 1.0f) * ((b.w - b.y) + 1.0f);
    }
    __syncwarp();
    if (i >= PRE_NMS) return;

    float4 bi4 = g_sboxes[i];
    float areai = ((bi4.z - bi4.x) + 1.0f) * ((bi4.w - bi4.y) + 1.0f);
    unsigned word = 0;
    int jmax = min(32, PRE_NMS - j0);
    for (int jj = 0; jj < jmax; ++jj) {
        int jg = j0 + jj;
        if (jg <= i) continue;
        float4 bj4 = bx[jj];
        float xx1 = fmaxf(bi4.x, bj4.x);
        float yy1 = fmaxf(bi4.y, bj4.y);
        float xx2 = fminf(bi4.z, bj4.z);
        float yy2 = fmaxf(bi4.w, bj4.w);              // reference bug
        float w = fmaxf(0.0f, (xx2 - xx1) + 1.0f);
        float h = fmaxf(0.0f, (yy2 - yy1) + 1.0f);
        float inter = w * h;
        float ov = inter / ((areai + ar[jj]) - inter);
        if (ov > 0.7f) word |= (1u << jj);
    }
    g_mask[i * NWORDS + bj] = word;
}

// ---------------------------------------------------------------------------
// Chunk-batched serial NMS scan: per 32-box chunk resolve intra-chunk order
// serially from diagonal words, then apply all surviving rows to future
// words in parallel. Identical suppression semantics to sequential NMS.
// ---------------------------------------------------------------------------
__global__ void __launch_bounds__(256) scan_kernel(float* __restrict__ out) {
    __shared__ unsigned keep[NWORDS];
    __shared__ unsigned sdiag[32];
    __shared__ unsigned curAlive;
    __shared__ int pref[NWORDS + 1];
    const int tid = threadIdx.x;
    if (tid < NWORDS) keep[tid] = (tid == NWORDS - 1) ? 0x0000FFFFu : 0xFFFFFFFFu;
    __syncthreads();

    for (int c = 0; c < NWORDS; ++c) {
        if (tid < 32) {
            int i = c * 32 + tid;
            sdiag[tid] = (i < PRE_NMS) ? g_mask[i * NWORDS + c] : 0u;
            __syncwarp();
            if (tid == 0) {
                unsigned alive = keep[c];
                unsigned rem = alive;
                while (rem) {
                    int b = __ffs(rem) - 1;
                    rem &= rem - 1u;
                    alive &= ~sdiag[b];        // bit b is alive (rem subset of alive)
                    rem &= alive;
                }
                keep[c] = alive;
                curAlive = alive;
            }
        }
        __syncthreads();
        unsigned alive = curAlive;
        if (alive) {
            for (int w2 = c + 1 + tid; w2 < NWORDS; w2 += 256) {
                unsigned nm = 0;
                unsigned a = alive;
                while (a) {
                    int b = __ffs(a) - 1;
                    a &= a - 1u;
                    nm |= g_mask[(c * 32 + b) * NWORDS + w2];
                }
                keep[w2] &= ~nm;
            }
        }
        __syncthreads();
    }

    if (tid == 0) {
        int run = 0;
        pref[0] = 0;
        for (int w = 0; w < NWORDS; ++w) { run += __popc(keep[w]); pref[w + 1] = run; }
    }
    __syncthreads();
    const int K = pref[NWORDS];

    for (int i = tid; i < PRE_NMS; i += 256) {
        int w = i >> 5, b = i & 31;
        unsigned kwv = keep[w];
        int kp = pref[w] + __popc(kwv & ((1u << b) - 1u));
        int pos = ((kwv >> b) & 1u) ? kp : (K + (i - kp));
        if (pos < POST_NMS) {
            float4 bb = g_sboxes[i];
            out[pos * 4 + 0] = bb.x;
            out[pos * 4 + 1] = bb.y;
            out[pos * 4 + 2] = (bb.z - bb.x) + 1.0f;
            out[pos * 4 + 3] = (bb.w - bb.y) + 1.0f;
        }
    }
}

// ---------------------------------------------------------------------------
extern "C" void kernel_launch(void* const* d_in, const int* in_sizes, int n_in,
                              void* d_out, int out_size) {
    const float* in_features = (const float*)d_in[0];
    const float* conv_w      = (const float*)d_in[1];
    const float* conv_b      = (const float*)d_in[2];
    const float* reg_w       = (const float*)d_in[3];
    const float* reg_b       = (const float*)d_in[4];
    const float* cls_w       = (const float*)d_in[5];
    const float* cls_b       = (const float*)d_in[6];
    float* out = (float*)d_out;

    cudaFuncSetAttribute(head_kernel, cudaFuncAttributeMaxDynamicSharedMemorySize,
                         (NCH * 64 + HB * NCH) * (int)sizeof(float));

    pad_kernel<<<(NCH * XP * XP + 255) / 256, 256>>>(in_features);
    wt_kernel<<<(NCH * NCH * 9 + 255) / 256, 256>>>(conv_w);
    conv_kernel<<<dim3(8, 50), 160>>>(conv_b);
    head_kernel<<<(FSZ * FSZ + HB - 1) / HB, 512,
                  (NCH * 64 + HB * NCH) * (int)sizeof(float)>>>(reg_w, reg_b, cls_w, cls_b);
    prefix_kernel<<<1, 1024>>>();
    scatter_kernel<<<(NKEYS + 255) / 256, 256>>>();
    localrank_kernel<<<(NKEYS + 255) / 256, 256>>>();
    mask_kernel<<<dim3(NWORDS, NWORDS), 32>>>();
    scan_kernel<<<1, 256>>>(out);
}

// round 7
// speedup vs baseline: 1.1048x; 1.1048x over previous
#include <cuda_runtime.h>
#include <math.h>

// ---------------------------------------------------------------------------
// RPN forward, batch -1 only.
// pad -> weight transpose (+hist zero) -> 3x3 conv (scalar FFMA, R5-proven) ->
// head GEMM (float4 LDS, k-split) + decode + histogram -> bucket prefix ->
// scatter -> exact local rank -> NMS mask (yy2=max bug) -> chunk scan -> out.
// ---------------------------------------------------------------------------

#define FSZ   50
#define XP    52
#define NCH   512
#define NKEYS 22500
#define PRE_NMS 6000
#define POST_NMS 300
#define NWORDS 188
#define NBUCK 65536

__device__ float  g_Xp[NCH * XP * XP];
__device__ float  g_Wt[9 * NCH * NCH];                 // [tap][ic][oc]
__device__ float  g_feat[FSZ * FSZ * NCH];             // [s][oc]
__device__ float4 g_boxes[NKEYS];
__device__ unsigned g_hi[NKEYS];
__device__ unsigned g_hist[NBUCK];
__device__ unsigned g_bcnt[NBUCK];
__device__ unsigned g_bstart[NBUCK + 1];
__device__ unsigned long long g_skey[NKEYS];
__device__ int    g_C;
__device__ float4 g_sboxes[PRE_NMS];
__device__ unsigned g_mask[PRE_NMS * NWORDS];

// ---------------------------------------------------------------------------
__global__ void pad_kernel(const float* __restrict__ in) {
    int idx = blockIdx.x * blockDim.x + threadIdx.x;
    if (idx >= NCH * XP * XP) return;
    int c = idx / (XP * XP);
    int r = idx - c * (XP * XP);
    int y = r / XP, x = r - y * XP;
    float v = 0.0f;
    if (y >= 1 && y <= FSZ && x >= 1 && x <= FSZ)
        v = in[((7 * NCH + c) * FSZ + (y - 1)) * FSZ + (x - 1)];
    g_Xp[idx] = v;
}

__global__ void wt_kernel(const float* __restrict__ w) {
    int idx = blockIdx.x * blockDim.x + threadIdx.x;
    if (idx < NBUCK) { g_hist[idx] = 0u; g_bcnt[idx] = 0u; }
    if (idx >= NCH * NCH * 9) return;
    int tap = idx % 9;
    int ic  = (idx / 9) % NCH;
    int oc  = idx / (9 * NCH);
    g_Wt[(tap * NCH + ic) * NCH + oc] = w[idx];
}

// ---------------------------------------------------------------------------
// 3x3 conv (R5-proven scalar FFMA): block = 64 oc x 50 w (one row h).
// ---------------------------------------------------------------------------
__global__ void __launch_bounds__(160) conv_kernel(const float* __restrict__ bias) {
    const int h   = blockIdx.y;
    const int ocb = blockIdx.x * 64;
    const int tid = threadIdx.x;
    const int to  = tid & 15;
    const int tw  = tid >> 4;
    const int wb  = tw * 5;

    __shared__ float As[8 * 9 * 64];
    __shared__ float Bs[8 * 3 * 52];

    float acc[4][5];
#pragma unroll
    for (int r = 0; r < 4; ++r)
#pragma unroll
        for (int j = 0; j < 5; ++j) acc[r][j] = 0.0f;

    for (int ic0 = 0; ic0 < NCH; ic0 += 8) {
#pragma unroll
        for (int it = 0; it < 8; ++it) {
            int idx = tid + it * 160;
            if (idx < 1152) {
                int rrow = idx >> 4, col = idx & 15;
                int t = rrow / 9, tap = rrow - t * 9;
                const float4* src = reinterpret_cast<const float4*>(
                    &g_Wt[(tap * NCH + ic0 + t) * NCH + ocb]);
                reinterpret_cast<float4*>(As)[idx] = src[col];
            }
        }
#pragma unroll
        for (int it = 0; it < 8; ++it) {
            int idx = tid + it * 160;
            if (idx < 1248) {
                int t = idx / 156;
                int rem = idx - t * 156;
                int kh = rem / 52, x = rem - kh * 52;
                Bs[idx] = g_Xp[(ic0 + t) * (XP * XP) + (h + kh) * XP + x];
            }
        }
        __syncthreads();

#pragma unroll 1
        for (int t = 0; t < 8; ++t) {
#pragma unroll
            for (int kh = 0; kh < 3; ++kh) {
                float b[7];
                const float* bp = &Bs[(t * 3 + kh) * 52 + wb];
#pragma unroll
                for (int j = 0; j < 7; ++j) b[j] = bp[j];
#pragma unroll
                for (int kw = 0; kw < 3; ++kw) {
                    float4 a4 = reinterpret_cast<const float4*>(As)[(t * 9 + kh * 3 + kw) * 16 + to];
#pragma unroll
                    for (int j = 0; j < 5; ++j) {
                        float bv = b[kw + j];
                        acc[0][j] += a4.x * bv;
                        acc[1][j] += a4.y * bv;
                        acc[2][j] += a4.z * bv;
                        acc[3][j] += a4.w * bv;
                    }
                }
            }
        }
        __syncthreads();
    }

    float4 bb = reinterpret_cast<const float4*>(bias)[(ocb >> 2) + to];
#pragma unroll
    for (int j = 0; j < 5; ++j) {
        int s = h * FSZ + wb + j;
        float4 v;
        v.x = acc[0][j] + bb.x;
        v.y = acc[1][j] + bb.y;
        v.z = acc[2][j] + bb.z;
        v.w = acc[3][j] + bb.w;
        v.x = (v.x >= 0.0f) ? v.x : 0.01f * v.x;
        v.y = (v.y >= 0.0f) ? v.y : 0.01f * v.y;
        v.z = (v.z >= 0.0f) ? v.z : 0.01f * v.z;
        v.w = (v.w >= 0.0f) ? v.w : 0.01f * v.w;
        *reinterpret_cast<float4*>(&g_feat[s * NCH + ocb + to * 4]) = v;
    }
}

// ---------------------------------------------------------------------------
// Head: float4-vectorized, W shared across 4 spatials, k split across 2 groups.
// dyn smem: Wsp[54][516] + ft[16][512]  = 144224 B.
// thread map: o = tid&63 (54 used), r = tid>>6: kh = r>>2 (k half), sg = r&3
// (4 spatial sub-groups x 4 spatials each).
// ---------------------------------------------------------------------------
#define HB 16
#define WPAD 516
__global__ void __launch_bounds__(512) head_kernel(const float* __restrict__ rw,
                                                   const float* __restrict__ rb,
                                                   const float* __restrict__ cw,
                                                   const float* __restrict__ cb) {
    extern __shared__ float sh[];
    float* Wsp = sh;                   // [54][WPAD]
    float* ft  = sh + 54 * WPAD;       // [HB][512]
    __shared__ float bb[54];
    __shared__ float par[2 * HB * 54];
    __shared__ float vals[HB * 54];

    const int tid = threadIdx.x;
    const int s0 = blockIdx.x * HB;

    for (int e = tid; e < 54 * NCH; e += 512) {
        int o = e >> 9, k = e & 511;
        Wsp[o * WPAD + k] = (o < 36) ? rw[o * NCH + k] : cw[(o - 36) * NCH + k];
    }
    if (tid < 54) bb[tid] = (tid < 36) ? rb[tid] : cb[tid - 36];
    for (int e = tid; e < HB * (NCH / 4); e += 512) {
        int sl = e >> 7, k4 = e & 127;
        int s = s0 + sl;
        float4 v = make_float4(0.f, 0.f, 0.f, 0.f);
        if (s < FSZ * FSZ) v = reinterpret_cast<const float4*>(g_feat + s * NCH)[k4];
        reinterpret_cast<float4*>(ft + sl * NCH)[k4] = v;
    }
    __syncthreads();

    const int o  = tid & 63;
    const int r  = tid >> 6;
    const int kh = r >> 2;       // 0/1 : k half
    const int sg = r & 3;        // spatial sub-group (4 spatials)
    if (o < 54) {
        const float4* w4 = reinterpret_cast<const float4*>(Wsp + o * WPAD) + kh * 64;
        const float4* f0 = reinterpret_cast<const float4*>(ft + (sg * 4 + 0) * NCH) + kh * 64;
        const float4* f1 = reinterpret_cast<const float4*>(ft + (sg * 4 + 1) * NCH) + kh * 64;
        const float4* f2 = reinterpret_cast<const float4*>(ft + (sg * 4 + 2) * NCH) + kh * 64;
        const float4* f3 = reinterpret_cast<const float4*>(ft + (sg * 4 + 3) * NCH) + kh * 64;
        float a0 = 0.f, a1 = 0.f, a2 = 0.f, a3 = 0.f;
#pragma unroll 4
        for (int c = 0; c < 64; ++c) {
            float4 w = w4[c];
            float4 f = f0[c];
            a0 += w.x * f.x; a0 += w.y * f.y; a0 += w.z * f.z; a0 += w.w * f.w;
            f = f1[c];
            a1 += w.x * f.x; a1 += w.y * f.y; a1 += w.z * f.z; a1 += w.w * f.w;
            f = f2[c];
            a2 += w.x * f.x; a2 += w.y * f.y; a2 += w.z * f.z; a2 += w.w * f.w;
            f = f3[c];
            a3 += w.x * f.x; a3 += w.y * f.y; a3 += w.z * f.z; a3 += w.w * f.w;
        }
        par[(kh * HB + sg * 4 + 0) * 54 + o] = a0;
        par[(kh * HB + sg * 4 + 1) * 54 + o] = a1;
        par[(kh * HB + sg * 4 + 2) * 54 + o] = a2;
        par[(kh * HB + sg * 4 + 3) * 54 + o] = a3;
    }
    __syncthreads();

    for (int e = tid; e < HB * 54; e += 512) {
        int oo = e % 54;
        vals[e] = (par[e] + par[HB * 54 + e]) + bb[oo];
    }
    __syncthreads();

    if (tid < HB * 9) {
        int sl = tid / 9, a = tid - sl * 9;
        int s = s0 + sl;
        if (s < FSZ * FSZ) {
            const float* v = &vals[sl * 54];
            float pr0 = v[a * 4 + 0], pr1 = v[a * 4 + 1];
            float pr2 = v[a * 4 + 2], pr3 = v[a * 4 + 3];
            float l0 = v[36 + a * 2], l1 = v[36 + a * 2 + 1];
            float m = fmaxf(l0, l1);
            float e0 = expf(l0 - m), e1 = expf(l1 - m);
            float score = e1 / (e0 + e1);

            int hh = s / FSZ, ww = s - hh * FSZ;
            float cx = (float)(16 * hh + 8);
            float cy = (float)(16 * ww + 8);
            int rr = a / 3, q = a - rr * 3;
            float basev = (q == 0) ? 128.0f : (q == 1 ? 256.0f : 512.0f);
            float sq_r  = (rr == 0) ? sqrtf(0.5f) : (rr == 1 ? 1.0f : sqrtf(2.0f));
            float sq_ir = (rr == 0) ? sqrtf(2.0f) : (rr == 1 ? 1.0f : sqrtf(0.5f));
            float hsv = basev * sq_r;
            float wsv = basev * sq_ir;
            float ax1 = cx - wsv * 0.5f;
            float ay1 = cy - hsv * 0.5f;

            float t1 = pr0 + ax1;
            float t2 = pr1 + ay1;
            float rx1 = fminf(fmaxf(t1, 0.0f), 799.0f);
            float ry1 = fminf(fmaxf(t2, 0.0f), 799.0f);
            float rx2 = fminf(fmaxf((t1 + pr2) + wsv, 0.0f), 799.0f);
            float ry2 = fminf(fmaxf((t2 + pr3) + hsv, 0.0f), 799.0f);

            float wv = pr2 + wsv, hv = pr3 + hsv;
            bool valid = (wv >= 16.0f) && (hv >= 16.0f);
            float sm = valid ? score : -INFINITY;

            unsigned u = __float_as_uint(sm);
            unsigned vm = (u & 0x80000000u) ? ~u : (u | 0x80000000u);
            unsigned hi = ~vm;
            int gi = s * 9 + a;
            g_hi[gi] = hi;
            atomicAdd(&g_hist[hi >> 16], 1u);
            g_boxes[gi] = make_float4(rx1, ry1, rx2, ry2);
        }
    }
}

// ---------------------------------------------------------------------------
__global__ void __launch_bounds__(1024) prefix_kernel() {
    const int tid = threadIdx.x;
    const int base = tid * 64;
    unsigned sum = 0;
    for (int k = 0; k < 64; ++k) sum += g_hist[base + k];

    unsigned lane = tid & 31, w = tid >> 5;
    unsigned inc = sum;
#pragma unroll
    for (int d = 1; d < 32; d <<= 1) {
        unsigned n = __shfl_up_sync(0xFFFFFFFFu, inc, d);
        if (lane >= d) inc += n;
    }
    __shared__ unsigned wsum[32];
    if (lane == 31) wsum[w] = inc;
    __syncthreads();
    if (w == 0) {
        unsigned x = wsum[lane];
#pragma unroll
        for (int d = 1; d < 32; d <<= 1) {
            unsigned n = __shfl_up_sync(0xFFFFFFFFu, x, d);
            if (lane >= d) x += n;
        }
        wsum[lane] = x;
    }
    __syncthreads();
    unsigned run = inc - sum + (w ? wsum[w - 1] : 0u);
    for (int k = 0; k < 64; ++k) {
        unsigned hcount = g_hist[base + k];
        g_bstart[base + k] = run;
        unsigned nx = run + hcount;
        if (run < PRE_NMS && nx >= PRE_NMS) g_C = (int)nx;
        run = nx;
    }
    if (tid == 1023) g_bstart[NBUCK] = run;
}

__global__ void __launch_bounds__(256) scatter_kernel() {
    int i = blockIdx.x * 256 + threadIdx.x;
    if (i >= NKEYS) return;
    unsigned hi = g_hi[i];
    unsigned b = hi >> 16;
    unsigned st = g_bstart[b];
    if (st < PRE_NMS) {
        unsigned pos = st + atomicAdd(&g_bcnt[b], 1u);
        g_skey[pos] = ((unsigned long long)hi << 15) | (unsigned)i;
    }
}

__global__ void __launch_bounds__(256) localrank_kernel() {
    int p = blockIdx.x * 256 + threadIdx.x;
    if (p >= g_C) return;
    unsigned long long key = g_skey[p];
    unsigned hi = (unsigned)(key >> 15);
    unsigned b = hi >> 16;
    int s = (int)g_bstart[b], e = (int)g_bstart[b + 1];
    int r = s;
    for (int q = s; q < e; ++q) r += (g_skey[q] < key) ? 1 : 0;
    if (r < PRE_NMS) g_sboxes[r] = g_boxes[key & 0x7FFFu];
}

// ---------------------------------------------------------------------------
__global__ void __launch_bounds__(32) mask_kernel() {
    const int bi = blockIdx.y, bj = blockIdx.x;
    if (bj < bi) return;
    const int t = threadIdx.x;
    const int i = bi * 32 + t;

    __shared__ float4 bx[32];
    __shared__ float ar[32];
    const int j0 = bj * 32;
    if (j0 + t < PRE_NMS) {
        float4 b = g_sboxes[j0 + t];
        bx[t] = b;
        ar[t] = ((b.z - b.x) + 1.0f) * ((b.w - b.y) + 1.0f);
    }
    __syncwarp();
    if (i >= PRE_NMS) return;

    float4 bi4 = g_sboxes[i];
    float areai = ((bi4.z - bi4.x) + 1.0f) * ((bi4.w - bi4.y) + 1.0f);
    unsigned word = 0;
    int jmax = min(32, PRE_NMS - j0);
    for (int jj = 0; jj < jmax; ++jj) {
        int jg = j0 + jj;
        if (jg <= i) continue;
        float4 bj4 = bx[jj];
        float xx1 = fmaxf(bi4.x, bj4.x);
        float yy1 = fmaxf(bi4.y, bj4.y);
        float xx2 = fminf(bi4.z, bj4.z);
        float yy2 = fmaxf(bi4.w, bj4.w);              // reference bug
        float w = fmaxf(0.0f, (xx2 - xx1) + 1.0f);
        float h = fmaxf(0.0f, (yy2 - yy1) + 1.0f);
        float inter = w * h;
        float ov = inter / ((areai + ar[jj]) - inter);
        if (ov > 0.7f) word |= (1u << jj);
    }
    g_mask[i * NWORDS + bj] = word;
}

// ---------------------------------------------------------------------------
__global__ void __launch_bounds__(256) scan_kernel(float* __restrict__ out) {
    __shared__ unsigned keep[NWORDS];
    __shared__ unsigned sdiag[32];
    __shared__ unsigned curAlive;
    __shared__ int pref[NWORDS + 1];
    const int tid = threadIdx.x;
    if (tid < NWORDS) keep[tid] = (tid == NWORDS - 1) ? 0x0000FFFFu : 0xFFFFFFFFu;
    __syncthreads();

    for (int c = 0; c < NWORDS; ++c) {
        if (tid < 32) {
            int i = c * 32 + tid;
            sdiag[tid] = (i < PRE_NMS) ? g_mask[i * NWORDS + c] : 0u;
            __syncwarp();
            if (tid == 0) {
                unsigned alive = keep[c];
                unsigned rem = alive;
                while (rem) {
                    int b = __ffs(rem) - 1;
                    rem &= rem - 1u;
                    alive &= ~sdiag[b];
                    rem &= alive;
                }
                keep[c] = alive;
                curAlive = alive;
            }
        }
        __syncthreads();
        unsigned alive = curAlive;
        if (alive) {
            for (int w2 = c + 1 + tid; w2 < NWORDS; w2 += 256) {
                unsigned nm = 0;
                unsigned a = alive;
                while (a) {
                    int b = __ffs(a) - 1;
                    a &= a - 1u;
                    nm |= g_mask[(c * 32 + b) * NWORDS + w2];
                }
                keep[w2] &= ~nm;
            }
        }
        __syncthreads();
    }

    if (tid == 0) {
        int run = 0;
        pref[0] = 0;
        for (int w = 0; w < NWORDS; ++w) { run += __popc(keep[w]); pref[w + 1] = run; }
    }
    __syncthreads();
    const int K = pref[NWORDS];

    for (int i = tid; i < PRE_NMS; i += 256) {
        int w = i >> 5, b = i & 31;
        unsigned kwv = keep[w];
        int kp = pref[w] + __popc(kwv & ((1u << b) - 1u));
        int pos = ((kwv >> b) & 1u) ? kp : (K + (i - kp));
        if (pos < POST_NMS) {
            float4 bb = g_sboxes[i];
            out[pos * 4 + 0] = bb.x;
            out[pos * 4 + 1] = bb.y;
            out[pos * 4 + 2] = (bb.z - bb.x) + 1.0f;
            out[pos * 4 + 3] = (bb.w - bb.y) + 1.0f;
        }
    }
}

// ---------------------------------------------------------------------------
extern "C" void kernel_launch(void* const* d_in, const int* in_sizes, int n_in,
                              void* d_out, int out_size) {
    const float* in_features = (const float*)d_in[0];
    const float* conv_w      = (const float*)d_in[1];
    const float* conv_b      = (const float*)d_in[2];
    const float* reg_w       = (const float*)d_in[3];
    const float* reg_b       = (const float*)d_in[4];
    const float* cls_w       = (const float*)d_in[5];
    const float* cls_b       = (const float*)d_in[6];
    float* out = (float*)d_out;

    const int head_smem = (54 * WPAD + HB * NCH) * (int)sizeof(float);
    cudaFuncSetAttribute(head_kernel, cudaFuncAttributeMaxDynamicSharedMemorySize, head_smem);

    pad_kernel<<<(NCH * XP * XP + 255) / 256, 256>>>(in_features);
    wt_kernel<<<(NCH * NCH * 9 + 255) / 256, 256>>>(conv_w);
    conv_kernel<<<dim3(8, 50), 160>>>(conv_b);
    head_kernel<<<(FSZ * FSZ + HB - 1) / HB, 512, head_smem>>>(reg_w, reg_b, cls_w, cls_b);
    prefix_kernel<<<1, 1024>>>();
    scatter_kernel<<<(NKEYS + 255) / 256, 256>>>();
    localrank_kernel<<<(NKEYS + 255) / 256, 256>>>();
    mask_kernel<<<dim3(NWORDS, NWORDS), 32>>>();
    scan_kernel<<<1, 256>>>(out);
}